// round 13
// baseline (speedup 1.0000x reference)
#include <cuda_runtime.h>
#include <cstddef>

#define TT_STEPS 365
#define NB 4000
#define LENF 15

// Scratch (allocation-free: __device__ globals)
__device__ float g_qsim[TT_STEPS * NB];   // mean-over-M runoff per (t, n)
__device__ float g_uh[LENF * NB];         // routing weights per (k, n)

#define SPB 5                              // steps per smem buffer
#define BSTRIDE 68                         // 64 floats + 4 pad -> conflict-free
#define STEP_PF (8 * BSTRIDE)              // 544 param floats / step / chain
#define BUF_PF (SPB * STEP_PF)             // 2720
#define CHAIN_PF (2 * BUF_PF)              // 5440 (two buffers)
#define FSTEP 32                           // forcing floats / step (24 + pad)
#define FBUF (SPB * FSTEP)                 // 160
#define FCHAIN (2 * FBUF)                  // 320
#define WARP_FLOATS (2 * CHAIN_PF + 2 * FCHAIN)   // 11520 floats = 46080 B
#define SCAN_SMEM (2 * WARP_FLOATS * 4)    // 2 warps/block = 92160 B

__device__ __forceinline__ void cp_async16(unsigned smem_addr, const void* gptr) {
    asm volatile("cp.async.cg.shared.global [%0], [%1], 16;\n"
                 :: "r"(smem_addr), "l"(gptr));
}
__device__ __forceinline__ void cp_commit() {
    asm volatile("cp.async.commit_group;\n");
}
#define CP_WAIT_GROUP(nrem) asm volatile("cp.async.wait_group %0;\n" :: "n"(nrem))

// -------------------------------------------------------------------------
// HBV single-chain step (exact reference op order)
// -------------------------------------------------------------------------
struct HBVState {
    float SNOWPACK, MELTWATER, SM, SUZ, SLZ;
};

__device__ __forceinline__ void hbv_step(HBVState& st,
                                         const float cur[14],
                                         float P, float Ta, float PET,
                                         int t, int n, int m) {
    const float BETA   = 1.0f   + 5.0f    * cur[0];
    const float FC     = 50.0f  + 950.0f  * cur[1];
    const float K0     = 0.05f  + 0.85f   * cur[2];
    const float K1     = 0.01f  + 0.49f   * cur[3];
    const float K2     = 0.001f + 0.199f  * cur[4];
    const float LP     = 0.2f   + 0.8f    * cur[5];
    const float PERC   =          10.0f   * cur[6];
    const float UZL    =          100.0f  * cur[7];
    const float TTp    = -2.5f  + 5.0f    * cur[8];
    const float CFMAX  = 0.5f   + 9.5f    * cur[9];
    const float CFR    =          0.1f    * cur[10];
    const float CWH    =          0.2f    * cur[11];
    const float BETAET = 0.3f   + 4.7f    * cur[12];
    const float Cc     =                    cur[13];

    const float RAIN = (Ta >= TTp) ? P : 0.0f;
    const float SNOW = (Ta <  TTp) ? P : 0.0f;
    st.SNOWPACK += SNOW;
    const float melt = fminf(fmaxf(CFMAX * (Ta - TTp), 0.0f), st.SNOWPACK);
    st.MELTWATER += melt;
    st.SNOWPACK = fmaxf(st.SNOWPACK - melt, 1e-5f);
    const float refreeze = fminf(fmaxf(CFR * CFMAX * (TTp - Ta), 0.0f), st.MELTWATER);
    st.SNOWPACK += refreeze;
    st.MELTWATER = fmaxf(st.MELTWATER - refreeze, 1e-5f);
    const float tosoil = fmaxf(st.MELTWATER - CWH * st.SNOWPACK, 0.0f);
    st.MELTWATER = fmaxf(st.MELTWATER - tosoil, 1e-5f);

    const float rFC   = __fdividef(1.0f, FC);
    const float rLPFC = __fdividef(1.0f, LP * FC);

    float soil_wet = __expf(BETA * __logf(st.SM * rFC));
    soil_wet = fminf(fmaxf(soil_wet, 0.0f), 1.0f);
    const float recharge = (RAIN + tosoil) * soil_wet;
    st.SM = st.SM + RAIN + tosoil - recharge;
    const float excess = fmaxf(st.SM - FC, 0.0f);
    st.SM = fmaxf(st.SM - excess, 1e-5f);

    float evapfactor = __expf(BETAET * __logf(st.SM * rLPFC));
    evapfactor = fminf(fmaxf(evapfactor, 0.0f), 1.0f);
    const float ETact = fminf(st.SM, PET * evapfactor);
    st.SM = fmaxf(st.SM - ETact, 1e-5f);

    const float capillary = fminf(st.SLZ, Cc * st.SLZ * (1.0f - fminf(st.SM * rFC, 1.0f)));
    st.SM += capillary;
    st.SLZ = fmaxf(st.SLZ - capillary, 1e-5f);

    st.SUZ += recharge + excess;
    const float PERCa = fminf(st.SUZ, PERC);
    st.SUZ -= PERCa;
    const float Q0 = K0 * fmaxf(st.SUZ - UZL, 0.0f);
    st.SUZ -= Q0;
    const float Q1 = K1 * st.SUZ;
    st.SUZ -= Q1;
    st.SLZ += PERCa;
    const float Q2 = K2 * st.SLZ;
    st.SLZ -= Q2;

    float q = Q0 + Q1 + Q2;
    q += __shfl_xor_sync(0xffffffffu, q, 1);
    q += __shfl_xor_sync(0xffffffffu, q, 2);
    if (m == 0)
        g_qsim[(size_t)t * NB + n] = 0.25f * q;
}

// -------------------------------------------------------------------------
// Kernel 1: HBV scan, TWO independent chains per thread.
// 8000 threads = 250 warps = 125 blocks x 64. Chain A: basins [0,2000),
// chain B: basins [2000,4000). Chain B's instructions fill chain A's
// dependency-stall bubbles inside one warp's in-order schedule.
// Params AND forcings staged in smem via a 2x5-step cp.async pipeline.
// -------------------------------------------------------------------------
__global__ void __launch_bounds__(64)
hbv_scan_kernel(const float* __restrict__ x,        // (T, N, 3)
                const float* __restrict__ praw) {   // (T, N, 16, 4)
    extern __shared__ __align__(16) float sp[];

    const int lane = threadIdx.x & 31;
    const int wrp  = threadIdx.x >> 5;                 // 0..1
    const int w    = blockIdx.x * 2 + wrp;             // global warp 0..249

    const int m       = lane & 3;
    const int n_local = lane >> 2;                     // 0..7
    const int n0A     = w * 8;                         // chain A first basin
    const int n0B     = 2000 + w * 8;                  // chain B first basin
    const int nA      = n0A + n_local;
    const int nB      = n0B + n_local;

    float* wbase = sp + wrp * WARP_FLOATS;
    float* pA = wbase;                     // [buf][step][chunk-swizzled]
    float* pB = wbase + CHAIN_PF;
    float* fA = wbase + 2 * CHAIN_PF;      // [buf][step][32]
    float* fB = fA + FCHAIN;

    // param producer addressing: lane L copies chunks c = j*32 + L (j<4)
    unsigned pdstA[4], pdstB[4];
    const float* pgA[4];
    const float* pgB[4];
#pragma unroll
    for (int j = 0; j < 4; ++j) {
        const int c = j * 32 + lane;
        const unsigned off = (c >> 4) * BSTRIDE + (c & 15) * 4;
        pdstA[j] = (unsigned)__cvta_generic_to_shared(pA + off);
        pdstB[j] = (unsigned)__cvta_generic_to_shared(pB + off);
        pgA[j] = praw + (size_t)n0A * 64 + (size_t)c * 4;
        pgB[j] = praw + (size_t)n0B * 64 + (size_t)c * 4;
    }
    // forcing producer: lanes 0..5 copy 16B chunks (96 B per chain-step)
    const unsigned fdstA = (unsigned)__cvta_generic_to_shared(fA + lane * 4);
    const unsigned fdstB = (unsigned)__cvta_generic_to_shared(fB + lane * 4);
    const float* fgA = x + (size_t)n0A * 3 + lane * 4;
    const float* fgB = x + (size_t)n0B * 3 + lane * 4;

    const unsigned step_pb = STEP_PF * 4;
    const unsigned buf_pb  = BUF_PF * 4;
    const unsigned fstep_b = FSTEP * 4;
    const unsigned fbuf_b  = FBUF * 4;

    // consumer base pointers
    const float* prdA = pA + n_local * BSTRIDE + m;
    const float* prdB = pB + n_local * BSTRIDE + m;
    const float* frdA = fA + n_local * 3;
    const float* frdB = fB + n_local * 3;

    HBVState stA = {0.001f, 0.001f, 0.001f, 0.001f, 0.001f};
    HBVState stB = {0.001f, 0.001f, 0.001f, 0.001f, 0.001f};

#define FILL_BUF(BSEL, TBASE)                                              \
    {                                                                      \
        _Pragma("unroll")                                                  \
        for (int s_ = 0; s_ < SPB; ++s_) {                                 \
            const int tn_ = ((TBASE) + s_ < TT_STEPS) ? (TBASE) + s_       \
                                                      : (TT_STEPS - 1);    \
            const size_t poff_ = (size_t)tn_ * (NB * 64);                  \
            _Pragma("unroll")                                              \
            for (int j_ = 0; j_ < 4; ++j_) {                               \
                cp_async16(pdstA[j_] + (BSEL) * buf_pb + s_ * step_pb,     \
                           pgA[j_] + poff_);                               \
                cp_async16(pdstB[j_] + (BSEL) * buf_pb + s_ * step_pb,     \
                           pgB[j_] + poff_);                               \
            }                                                              \
            if (lane < 6) {                                                \
                const size_t xoff_ = (size_t)tn_ * (NB * 3);               \
                cp_async16(fdstA + (BSEL) * fbuf_b + s_ * fstep_b,         \
                           fgA + xoff_);                                   \
                cp_async16(fdstB + (BSEL) * fbuf_b + s_ * fstep_b,         \
                           fgB + xoff_);                                   \
            }                                                              \
        }                                                                  \
        cp_commit();                                                       \
    }

#define PROCESS_BUF(BSEL, TBASE)                                           \
    {                                                                      \
        _Pragma("unroll")                                                  \
        for (int s_ = 0; s_ < SPB; ++s_) {                                 \
            float curA_[14], curB_[14];                                    \
            const float* psA_ = prdA + (BSEL) * BUF_PF + s_ * STEP_PF;     \
            const float* psB_ = prdB + (BSEL) * BUF_PF + s_ * STEP_PF;     \
            _Pragma("unroll")                                              \
            for (int i_ = 0; i_ < 14; ++i_) {                              \
                curA_[i_] = psA_[i_ * 4];                                  \
                curB_[i_] = psB_[i_ * 4];                                  \
            }                                                              \
            const float* ffA_ = frdA + (BSEL) * FBUF + s_ * FSTEP;         \
            const float* ffB_ = frdB + (BSEL) * FBUF + s_ * FSTEP;         \
            hbv_step(stA, curA_, ffA_[0], ffA_[1], ffA_[2],                \
                     (TBASE) + s_, nA, m);                                 \
            hbv_step(stB, curB_, ffB_[0], ffB_[1], ffB_[2],                \
                     (TBASE) + s_, nB, m);                                 \
        }                                                                  \
    }

    // prologue: buffer0 <- t 0..4, buffer1 <- t 5..9
    FILL_BUF(0, 0);
    FILL_BUF(1, SPB);

    // 36 iterations x 10 steps + 5-step tail = 365
    for (int i = 0; i < 36; ++i) {
        const int tb = i * 10;

        CP_WAIT_GROUP(1);
        __syncwarp();
        PROCESS_BUF(0, tb);
        FILL_BUF(0, tb + 10);

        CP_WAIT_GROUP(1);
        __syncwarp();
        PROCESS_BUF(1, tb + SPB);
        FILL_BUF(1, tb + 15);
    }

    CP_WAIT_GROUP(1);
    __syncwarp();
    PROCESS_BUF(0, 360);
    CP_WAIT_GROUP(0);          // drain before exit
}

// -------------------------------------------------------------------------
// Kernel 2: gamma unit-hydrograph weights per basin (normalized).
// -------------------------------------------------------------------------
__global__ void uh_kernel(const float* __restrict__ conv) {
    const int n = blockIdx.x * blockDim.x + threadIdx.x;
    if (n >= NB) return;
    const float a = conv[n * 2 + 0] * 2.9f;
    const float b = conv[n * 2 + 1] * 6.5f;
    const float aa    = fmaxf(a, 0.0f) + 0.1f;
    const float theta = fmaxf(b, 0.0f) + 0.5f;
    const float lg = lgammaf(aa);
    const float lt = logf(theta);
    const float rth = 1.0f / theta;

    float w[LENF];
    float s = 0.0f;
#pragma unroll
    for (int k = 0; k < LENF; ++k) {
        const float tt = 0.5f + (float)k;
        w[k] = expf(-lg - aa * lt + (aa - 1.0f) * logf(tt) - tt * rth);
        s += w[k];
    }
    const float rs = 1.0f / s;
#pragma unroll
    for (int k = 0; k < LENF; ++k)
        g_uh[k * NB + n] = w[k] * rs;
}

// -------------------------------------------------------------------------
// Kernel 3: 15-tap causal FIR routing. One thread per (t, n) output.
// -------------------------------------------------------------------------
__global__ void rout_kernel(float* __restrict__ out) {
    const int idx = blockIdx.x * blockDim.x + threadIdx.x;
    if (idx >= TT_STEPS * NB) return;
    const int t = idx / NB;
    const int n = idx - t * NB;

    float acc = 0.0f;
#pragma unroll
    for (int k = 0; k < LENF; ++k) {
        if (k <= t)
            acc += __ldg(&g_uh[k * NB + n]) * __ldg(&g_qsim[(size_t)(t - k) * NB + n]);
    }
    out[idx] = acc;
}

// -------------------------------------------------------------------------
extern "C" void kernel_launch(void* const* d_in, const int* in_sizes, int n_in,
                              void* d_out, int out_size) {
    const float* x    = (const float*)d_in[0];   // (365, 4000, 3)
    const float* praw = (const float*)d_in[1];   // (365, 4000, 16, 4)
    const float* conv = (const float*)d_in[2];   // (4000, 2)
    float* out = (float*)d_out;                  // (365, 4000)

    // 92 KB dynamic smem (> 48 KB default): opt in (idempotent, capture-safe)
    cudaFuncSetAttribute(hbv_scan_kernel,
                         cudaFuncAttributeMaxDynamicSharedMemorySize, SCAN_SMEM);

    hbv_scan_kernel<<<125, 64, SCAN_SMEM>>>(x, praw);
    uh_kernel<<<(NB + 127) / 128, 128>>>(conv);
    rout_kernel<<<(TT_STEPS * NB + 255) / 256, 256>>>(out);
}

// round 14
// speedup vs baseline: 1.8971x; 1.8971x over previous
#include <cuda_runtime.h>
#include <cstddef>

#define TT_STEPS 365
#define NB 4000
#define LENF 15

// Scratch (allocation-free: __device__ globals)
__device__ float g_qsim[TT_STEPS * NB];   // mean-over-M runoff per (t, n)
__device__ float g_uh[LENF * NB];         // routing weights per (k, n)

#define SPB 5                             // steps per smem buffer
#define BSTRIDE 68                        // 64 floats + 4 pad -> conflict-free LDS
#define STAGE_FLOATS (8 * BSTRIDE)        // 544 floats per step per warp
#define BUF_FLOATS (SPB * STAGE_FLOATS)   // 2720 floats per buffer
#define WARP_SMEM (2 * BUF_FLOATS)        // two buffers per warp
#define SCAN_SMEM (4 * WARP_SMEM * 4)     // 4 warps * 21760 B = 87040 B

__device__ __forceinline__ void cp_async16(unsigned smem_addr, const void* gptr) {
    asm volatile("cp.async.cg.shared.global [%0], [%1], 16;\n"
                 :: "r"(smem_addr), "l"(gptr));
}
__device__ __forceinline__ void cp_commit() {
    asm volatile("cp.async.commit_group;\n");
}
#define CP_WAIT_GROUP(nrem) asm volatile("cp.async.wait_group %0;\n" :: "n"(nrem))

// -------------------------------------------------------------------------
// Kernel 1: HBV scan. One thread per (n, m) chain; 16000 threads, 125
// blocks x 128 -> 1 warp per SMSP on every SM (proven wall-optimal:
// R10/R12 showed any repacking raises the wall). Barriers once per
// 5 steps (two 5-step smem buffers, one cp.async group each).
// NEW: __launch_bounds__(128,1) frees the register budget so ptxas can
// hoist LDS/scaling across steps; hbv_step algebra shortened (<=1 ulp).
// -------------------------------------------------------------------------
struct HBVState {
    float SNOWPACK, MELTWATER, SM, SUZ, SLZ;
};

__device__ __forceinline__ void hbv_step(HBVState& st,
                                         const float cur[14],
                                         float P, float Ta, float PET,
                                         int t, int n, int m) {
    const float BETA   = 1.0f   + 5.0f    * cur[0];
    const float FC     = 50.0f  + 950.0f  * cur[1];
    const float K0     = 0.05f  + 0.85f   * cur[2];
    const float K1     = 0.01f  + 0.49f   * cur[3];
    const float K2     = 0.001f + 0.199f  * cur[4];
    const float LP     = 0.2f   + 0.8f    * cur[5];
    const float PERC   =          10.0f   * cur[6];
    const float UZL    =          100.0f  * cur[7];
    const float TTp    = -2.5f  + 5.0f    * cur[8];
    const float CFMAX  = 0.5f   + 9.5f    * cur[9];
    const float CFR    =          0.1f    * cur[10];
    const float CWH    =          0.2f    * cur[11];
    const float BETAET = 0.3f   + 4.7f    * cur[12];
    const float Cc     =                    cur[13];

    // param-only (off the state chain; scheduler can hoist freely)
    const float rFC   = __fdividef(1.0f, FC);
    const float rLPFC = __fdividef(1.0f, LP * FC);
    const float aM    = fmaxf(CFMAX * (Ta - TTp), 0.0f);         // melt cap
    const float bR    = fmaxf(CFR * CFMAX * (TTp - Ta), 0.0f);   // refreeze cap
    const float RAIN  = (Ta >= TTp) ? P : 0.0f;
    const float SNOW  = (Ta <  TTp) ? P : 0.0f;

    // snow / meltwater (X - min(a,X) == max(X-a,0) rewrites, exact)
    const float SP1  = st.SNOWPACK + SNOW;
    const float melt = fminf(aM, SP1);
    const float MW2  = st.MELTWATER + melt;
    const float SP2  = fmaxf(SP1 - aM, 1e-5f);
    const float refreeze = fminf(bR, MW2);
    st.SNOWPACK = SP2 + refreeze;
    const float MW3 = fmaxf(MW2 - bR, 1e-5f);
    const float cM  = CWH * st.SNOWPACK;
    const float tosoil = fmaxf(MW3 - cM, 0.0f);
    st.MELTWATER = fmaxf(fminf(MW3, cM), 1e-5f);

    // soil moisture
    const float rt = RAIN + tosoil;
    float sw = __expf(BETA * __logf(st.SM * rFC));
    sw = fminf(fmaxf(sw, 0.0f), 1.0f);
    const float recharge = rt * sw;
    const float SM1 = st.SM + rt - recharge;
    const float excess = fmaxf(SM1 - FC, 0.0f);
    const float SM2 = fmaxf(fminf(SM1, FC), 1e-5f);      // == max(SM1-excess,eps)

    float ef = __expf(BETAET * __logf(SM2 * rLPFC));
    ef = fminf(fmaxf(ef, 0.0f), 1.0f);
    const float SM3 = fmaxf(SM2 - PET * ef, 1e-5f);      // == max(SM2-ETact,eps)

    const float cap = fminf(st.SLZ, Cc * st.SLZ * (1.0f - fminf(SM3 * rFC, 1.0f)));
    st.SM  = SM3 + cap;
    const float SLZ2 = fmaxf(st.SLZ - cap, 1e-5f);

    // runoff
    const float SUZ1  = st.SUZ + recharge + excess;
    const float PERCa = fminf(SUZ1, PERC);
    const float SUZ2  = SUZ1 - PERCa;
    const float Q0 = K0 * fmaxf(SUZ2 - UZL, 0.0f);
    const float SUZ3 = SUZ2 - Q0;
    const float Q1 = K1 * SUZ3;
    st.SUZ = SUZ3 - Q1;
    const float SLZ3 = SLZ2 + PERCa;
    const float Q2 = K2 * SLZ3;
    st.SLZ = SLZ3 - Q2;

    // mean over the 4 ensemble members (quad = adjacent lanes)
    float q = Q0 + Q1 + Q2;
    q += __shfl_xor_sync(0xffffffffu, q, 1);
    q += __shfl_xor_sync(0xffffffffu, q, 2);
    if (m == 0)
        g_qsim[(size_t)t * NB + n] = 0.25f * q;
}

__global__ void __launch_bounds__(128, 1)
hbv_scan_kernel(const float* __restrict__ x,        // (T, N, 3)
                const float* __restrict__ praw) {   // (T, N, 16, 4)
    extern __shared__ __align__(16) float sp[];     // [4 warps][2][BUF_FLOATS]

    const int lane = threadIdx.x & 31;
    const int wrp  = threadIdx.x >> 5;
    const int tid  = blockIdx.x * 128 + threadIdx.x;   // exactly 16000

    const int n       = tid >> 2;        // consumer: basin
    const int m       = tid & 3;         // consumer: ensemble member
    const int n_local = lane >> 2;       // basin within warp (0..7)
    const int n0      = (tid >> 5) * 8;  // warp's first basin

    float* wbase = sp + wrp * WARP_SMEM;

    // producer: lane L copies 16-byte chunks c = j*32 + L (j = 0..3) of the
    // warp's 2048-byte param block (per step)
    unsigned sdst[4];
    const float* gsrc[4];
#pragma unroll
    for (int j = 0; j < 4; ++j) {
        const int c = j * 32 + lane;
        sdst[j] = (unsigned)__cvta_generic_to_shared(
                      wbase + (c >> 4) * BSTRIDE + (c & 15) * 4);
        gsrc[j] = praw + (size_t)n0 * 64 + (size_t)c * 4;
    }
    const unsigned stage_bytes = STAGE_FLOATS * 4;
    const unsigned buf_bytes   = BUF_FLOATS * 4;

    const float* xbase = x + (size_t)n * 3;
    const float* prd0  = wbase + n_local * BSTRIDE + m;            // buffer 0
    const float* prd1  = prd0 + BUF_FLOATS;                        // buffer 1

    HBVState st = {0.001f, 0.001f, 0.001f, 0.001f, 0.001f};

    float fb0[SPB][3], fb1[SPB][3];      // forcings, statically indexed

#define FILL_BUF(BSEL, TBASE, FB)                                          \
    {                                                                      \
        _Pragma("unroll")                                                  \
        for (int s_ = 0; s_ < SPB; ++s_) {                                 \
            const int tn_ = ((TBASE) + s_ < TT_STEPS) ? (TBASE) + s_       \
                                                      : (TT_STEPS - 1);    \
            const size_t poff_ = (size_t)tn_ * (NB * 64);                  \
            _Pragma("unroll")                                              \
            for (int j_ = 0; j_ < 4; ++j_)                                 \
                cp_async16(sdst[j_] + (BSEL) * buf_bytes                   \
                                    + s_ * stage_bytes,                    \
                           gsrc[j_] + poff_);                              \
            const size_t xoff_ = (size_t)tn_ * (NB * 3);                   \
            _Pragma("unroll")                                              \
            for (int c_ = 0; c_ < 3; ++c_)                                 \
                FB[s_][c_] = __ldg(xbase + xoff_ + c_);                    \
        }                                                                  \
        cp_commit();                                                       \
    }

#define PROCESS_BUF(PRD, TBASE, FB)                                        \
    {                                                                      \
        _Pragma("unroll")                                                  \
        for (int s_ = 0; s_ < SPB; ++s_) {                                 \
            float cur_[14];                                                \
            const float* ps_ = (PRD) + s_ * STAGE_FLOATS;                  \
            _Pragma("unroll")                                              \
            for (int i_ = 0; i_ < 14; ++i_)                                \
                cur_[i_] = ps_[i_ * 4];                                    \
            hbv_step(st, cur_, FB[s_][0], FB[s_][1], FB[s_][2],            \
                     (TBASE) + s_, n, m);                                  \
        }                                                                  \
    }

    // prologue: buffer0 <- t 0..4 (group0), buffer1 <- t 5..9 (group1)
    FILL_BUF(0, 0, fb0);
    FILL_BUF(1, SPB, fb1);

    // 36 iterations x 10 steps + 5-step tail = 365
    for (int i = 0; i < 36; ++i) {
        const int tb = i * 10;

        CP_WAIT_GROUP(1);
        __syncwarp();
        PROCESS_BUF(prd0, tb, fb0);
        FILL_BUF(0, tb + 10, fb0);

        CP_WAIT_GROUP(1);
        __syncwarp();
        PROCESS_BUF(prd1, tb + SPB, fb1);
        FILL_BUF(1, tb + 15, fb1);
    }

    // tail: steps 360..364 live in buffer0 (refilled at i=35)
    CP_WAIT_GROUP(1);
    __syncwarp();
    PROCESS_BUF(prd0, 360, fb0);
    CP_WAIT_GROUP(0);         // drain before exit
}

// -------------------------------------------------------------------------
// Kernel 2: gamma unit-hydrograph weights per basin (normalized).
// -------------------------------------------------------------------------
__global__ void uh_kernel(const float* __restrict__ conv) {
    const int n = blockIdx.x * blockDim.x + threadIdx.x;
    if (n >= NB) return;
    const float a = conv[n * 2 + 0] * 2.9f;
    const float b = conv[n * 2 + 1] * 6.5f;
    const float aa    = fmaxf(a, 0.0f) + 0.1f;
    const float theta = fmaxf(b, 0.0f) + 0.5f;
    const float lg = lgammaf(aa);
    const float lt = logf(theta);
    const float rth = 1.0f / theta;

    float w[LENF];
    float s = 0.0f;
#pragma unroll
    for (int k = 0; k < LENF; ++k) {
        const float tt = 0.5f + (float)k;
        w[k] = expf(-lg - aa * lt + (aa - 1.0f) * logf(tt) - tt * rth);
        s += w[k];
    }
    const float rs = 1.0f / s;
#pragma unroll
    for (int k = 0; k < LENF; ++k)
        g_uh[k * NB + n] = w[k] * rs;
}

// -------------------------------------------------------------------------
// Kernel 3: 15-tap causal FIR routing, t-tiled x8.
// Each thread produces 8 consecutive t for one basin n, keeping the
// 22-sample qsim window and 15 uh taps in registers -> ~3x less L2 traffic.
// -------------------------------------------------------------------------
#define TTILE 8
#define NT_TILES ((TT_STEPS + TTILE - 1) / TTILE)   // 46

__global__ void rout_kernel(float* __restrict__ out) {
    const int n = blockIdx.x * blockDim.x + threadIdx.x;
    if (n >= NB) return;
    const int t0 = blockIdx.y * TTILE;

    float uh[LENF];
#pragma unroll
    for (int k = 0; k < LENF; ++k)
        uh[k] = __ldg(&g_uh[k * NB + n]);

    float qs[TTILE + LENF - 1];          // qsim[t0-14 .. t0+7]
#pragma unroll
    for (int i = 0; i < TTILE + LENF - 1; ++i) {
        const int tq = t0 - (LENF - 1) + i;
        qs[i] = (tq >= 0 && tq < TT_STEPS) ? __ldg(&g_qsim[(size_t)tq * NB + n])
                                           : 0.0f;
    }

#pragma unroll
    for (int j = 0; j < TTILE; ++j) {
        const int t = t0 + j;
        if (t < TT_STEPS) {
            float acc = 0.0f;
#pragma unroll
            for (int k = 0; k < LENF; ++k)
                acc += uh[k] * qs[j + (LENF - 1) - k];
            out[(size_t)t * NB + n] = acc;
        }
    }
}

// -------------------------------------------------------------------------
extern "C" void kernel_launch(void* const* d_in, const int* in_sizes, int n_in,
                              void* d_out, int out_size) {
    const float* x    = (const float*)d_in[0];   // (365, 4000, 3)
    const float* praw = (const float*)d_in[1];   // (365, 4000, 16, 4)
    const float* conv = (const float*)d_in[2];   // (4000, 2)
    float* out = (float*)d_out;                  // (365, 4000)

    // 87 KB dynamic smem (> 48 KB default): opt in (idempotent, capture-safe)
    cudaFuncSetAttribute(hbv_scan_kernel,
                         cudaFuncAttributeMaxDynamicSharedMemorySize, SCAN_SMEM);

    hbv_scan_kernel<<<125, 128, SCAN_SMEM>>>(x, praw);
    uh_kernel<<<(NB + 127) / 128, 128>>>(conv);

    dim3 rgrid((NB + 255) / 256, NT_TILES);
    rout_kernel<<<rgrid, 256>>>(out);
}

// round 15
// speedup vs baseline: 1.9028x; 1.0030x over previous
#include <cuda_runtime.h>
#include <cstddef>

#define TT_STEPS 365
#define NB 4000
#define LENF 15

// Scratch (allocation-free: __device__ globals)
__device__ float g_qsim[TT_STEPS * NB];   // mean-over-M runoff per (t, n)
__device__ float g_uh[LENF * NB];         // routing weights per (k, n)

#define SPB 5                             // steps per smem buffer
#define BSTRIDE 68                        // 64 floats + 4 pad -> conflict-free LDS
#define STAGE_FLOATS (8 * BSTRIDE)        // 544 floats per step per warp
#define BUF_FLOATS (SPB * STAGE_FLOATS)   // 2720 floats per buffer
#define WARP_SMEM (2 * BUF_FLOATS)        // two buffers per warp
#define SCAN_SMEM (4 * WARP_SMEM * 4)     // 4 warps * 21760 B = 87040 B

__device__ __forceinline__ void cp_async16(unsigned smem_addr, const void* gptr) {
    asm volatile("cp.async.cg.shared.global [%0], [%1], 16;\n"
                 :: "r"(smem_addr), "l"(gptr));
}
__device__ __forceinline__ void cp_commit() {
    asm volatile("cp.async.commit_group;\n");
}
#define CP_WAIT_GROUP(nrem) asm volatile("cp.async.wait_group %0;\n" :: "n"(nrem))

// x^e for x > 0 via direct lg2/ex2 (what __expf(e*__logf(x)) compiles to,
// minus the two ln2/log2e constant FMULs on the critical chain)
__device__ __forceinline__ float pow_fast(float x, float e) {
    float l, r;
    asm("lg2.approx.f32 %0, %1;" : "=f"(l) : "f"(x));
    l *= e;
    asm("ex2.approx.f32 %0, %1;" : "=f"(r) : "f"(l));
    return r;
}

// -------------------------------------------------------------------------
// HBV step split into PREP (param/forcing-only, no state dependence) and
// CHAIN (the true serial recurrence). PREP of step t+1 is computed while
// CHAIN of step t runs -> manual cross-step interleave.
// -------------------------------------------------------------------------
struct HBVState {
    float SNOWPACK, MELTWATER, SM, SUZ, SLZ;
};

struct Prep {
    float RAIN, SNOW, aM, bR, CWH, FC, rFC, rLPFC,
          BETA, BETAET, PETv, PERC, UZL, K0, K1, K2, Cc;
};

__device__ __forceinline__ Prep prep_step(const float* __restrict__ ps,
                                          float P, float Ta, float PET) {
    float c[14];
#pragma unroll
    for (int i = 0; i < 14; ++i)
        c[i] = ps[i * 4];
    Prep p;
    p.BETA   = 1.0f   + 5.0f    * c[0];
    p.FC     = 50.0f  + 950.0f  * c[1];
    p.K0     = 0.05f  + 0.85f   * c[2];
    p.K1     = 0.01f  + 0.49f   * c[3];
    p.K2     = 0.001f + 0.199f  * c[4];
    const float LP     = 0.2f + 0.8f * c[5];
    p.PERC   = 10.0f  * c[6];
    p.UZL    = 100.0f * c[7];
    const float TTp    = -2.5f + 5.0f * c[8];
    const float CFMAX  = 0.5f + 9.5f * c[9];
    const float CFR    = 0.1f * c[10];
    p.CWH    = 0.2f   * c[11];
    p.BETAET = 0.3f   + 4.7f * c[12];
    p.Cc     = c[13];
    p.rFC    = __fdividef(1.0f, p.FC);
    p.rLPFC  = __fdividef(1.0f, LP * p.FC);
    p.aM     = fmaxf(CFMAX * (Ta - TTp), 0.0f);
    p.bR     = fmaxf(CFR * CFMAX * (TTp - Ta), 0.0f);
    p.RAIN   = (Ta >= TTp) ? P : 0.0f;
    p.SNOW   = (Ta <  TTp) ? P : 0.0f;
    p.PETv   = PET;
    return p;
}

__device__ __forceinline__ void chain_step(HBVState& st, const Prep& p,
                                           int t, int n, int m) {
    // snow / meltwater (X - min(a,X) == max(X-a,0) rewrites, exact)
    const float SP1  = st.SNOWPACK + p.SNOW;
    const float melt = fminf(p.aM, SP1);
    const float MW2  = st.MELTWATER + melt;
    const float SP2  = fmaxf(SP1 - p.aM, 1e-5f);
    const float refreeze = fminf(p.bR, MW2);
    st.SNOWPACK = SP2 + refreeze;
    const float MW3 = fmaxf(MW2 - p.bR, 1e-5f);
    const float cM  = p.CWH * st.SNOWPACK;
    const float tosoil = fmaxf(MW3 - cM, 0.0f);
    st.MELTWATER = fmaxf(fminf(MW3, cM), 1e-5f);

    // soil moisture (pow outputs are >= 0, so only the upper clip is needed)
    const float rt = p.RAIN + tosoil;
    const float sw = fminf(pow_fast(st.SM * p.rFC, p.BETA), 1.0f);
    const float recharge = rt * sw;
    const float SM1 = st.SM + rt - recharge;
    const float excess = fmaxf(SM1 - p.FC, 0.0f);
    const float SM2 = fmaxf(fminf(SM1, p.FC), 1e-5f);

    const float ef = fminf(pow_fast(SM2 * p.rLPFC, p.BETAET), 1.0f);
    const float SM3 = fmaxf(SM2 - p.PETv * ef, 1e-5f);

    const float cap = fminf(st.SLZ,
                            p.Cc * st.SLZ * (1.0f - fminf(SM3 * p.rFC, 1.0f)));
    st.SM = SM3 + cap;
    const float SLZ2 = fmaxf(st.SLZ - cap, 1e-5f);

    // runoff
    const float SUZ1  = st.SUZ + recharge + excess;
    const float PERCa = fminf(SUZ1, p.PERC);
    const float SUZ2  = SUZ1 - PERCa;
    const float Q0 = p.K0 * fmaxf(SUZ2 - p.UZL, 0.0f);
    const float SUZ3 = SUZ2 - Q0;
    const float Q1 = p.K1 * SUZ3;
    st.SUZ = SUZ3 - Q1;
    const float SLZ3 = SLZ2 + PERCa;
    const float Q2 = p.K2 * SLZ3;
    st.SLZ = SLZ3 - Q2;

    // mean over the 4 ensemble members (quad = adjacent lanes)
    float q = Q0 + Q1 + Q2;
    q += __shfl_xor_sync(0xffffffffu, q, 1);
    q += __shfl_xor_sync(0xffffffffu, q, 2);
    if (m == 0)
        g_qsim[(size_t)t * NB + n] = 0.25f * q;
}

// -------------------------------------------------------------------------
// Kernel 1: HBV scan. One thread per (n, m) chain; 16000 threads, 125
// blocks x 128 -> 1 warp per SMSP on every SM (proven wall-optimal).
// Two 5-step smem buffers, one cp.async group each; within the 5-step
// region, PREP(s+1) is issued before CHAIN(s) -> manual interleave.
// -------------------------------------------------------------------------
__global__ void __launch_bounds__(128, 1)
hbv_scan_kernel(const float* __restrict__ x,        // (T, N, 3)
                const float* __restrict__ praw) {   // (T, N, 16, 4)
    extern __shared__ __align__(16) float sp[];     // [4 warps][2][BUF_FLOATS]

    const int lane = threadIdx.x & 31;
    const int wrp  = threadIdx.x >> 5;
    const int tid  = blockIdx.x * 128 + threadIdx.x;   // exactly 16000

    const int n       = tid >> 2;        // consumer: basin
    const int m       = tid & 3;         // consumer: ensemble member
    const int n_local = lane >> 2;       // basin within warp (0..7)
    const int n0      = (tid >> 5) * 8;  // warp's first basin

    float* wbase = sp + wrp * WARP_SMEM;

    // producer: lane L copies 16-byte chunks c = j*32 + L (j = 0..3) of the
    // warp's 2048-byte param block (per step)
    unsigned sdst[4];
    const float* gsrc[4];
#pragma unroll
    for (int j = 0; j < 4; ++j) {
        const int c = j * 32 + lane;
        sdst[j] = (unsigned)__cvta_generic_to_shared(
                      wbase + (c >> 4) * BSTRIDE + (c & 15) * 4);
        gsrc[j] = praw + (size_t)n0 * 64 + (size_t)c * 4;
    }
    const unsigned stage_bytes = STAGE_FLOATS * 4;
    const unsigned buf_bytes   = BUF_FLOATS * 4;

    const float* xbase = x + (size_t)n * 3;
    const float* prd0  = wbase + n_local * BSTRIDE + m;            // buffer 0
    const float* prd1  = prd0 + BUF_FLOATS;                        // buffer 1

    HBVState st = {0.001f, 0.001f, 0.001f, 0.001f, 0.001f};

    float fb0[SPB][3], fb1[SPB][3];      // forcings, statically indexed

#define FILL_BUF(BSEL, TBASE, FB)                                          \
    {                                                                      \
        _Pragma("unroll")                                                  \
        for (int s_ = 0; s_ < SPB; ++s_) {                                 \
            const int tn_ = ((TBASE) + s_ < TT_STEPS) ? (TBASE) + s_       \
                                                      : (TT_STEPS - 1);    \
            const size_t poff_ = (size_t)tn_ * (NB * 64);                  \
            _Pragma("unroll")                                              \
            for (int j_ = 0; j_ < 4; ++j_)                                 \
                cp_async16(sdst[j_] + (BSEL) * buf_bytes                   \
                                    + s_ * stage_bytes,                    \
                           gsrc[j_] + poff_);                              \
            const size_t xoff_ = (size_t)tn_ * (NB * 3);                   \
            _Pragma("unroll")                                              \
            for (int c_ = 0; c_ < 3; ++c_)                                 \
                FB[s_][c_] = __ldg(xbase + xoff_ + c_);                    \
        }                                                                  \
        cp_commit();                                                       \
    }

// Software-pipelined: PREP of step s+1 textually precedes CHAIN of step s,
// so its LDS/FMA/RCP ops are available to fill CHAIN's MUFU/FMA shadows.
#define PROCESS_BUF(PRD, TBASE, FB)                                        \
    {                                                                      \
        Prep pc_ = prep_step((PRD), FB[0][0], FB[0][1], FB[0][2]);         \
        _Pragma("unroll")                                                  \
        for (int s_ = 0; s_ < SPB; ++s_) {                                 \
            Prep pn_ = pc_;                                                \
            if (s_ < SPB - 1)                                              \
                pn_ = prep_step((PRD) + (s_ + 1) * STAGE_FLOATS,           \
                                FB[s_ + 1][0], FB[s_ + 1][1],              \
                                FB[s_ + 1][2]);                            \
            chain_step(st, pc_, (TBASE) + s_, n, m);                       \
            pc_ = pn_;                                                     \
        }                                                                  \
    }

    // prologue: buffer0 <- t 0..4 (group0), buffer1 <- t 5..9 (group1)
    FILL_BUF(0, 0, fb0);
    FILL_BUF(1, SPB, fb1);

    // 36 iterations x 10 steps + 5-step tail = 365
    for (int i = 0; i < 36; ++i) {
        const int tb = i * 10;

        CP_WAIT_GROUP(1);
        __syncwarp();
        PROCESS_BUF(prd0, tb, fb0);
        FILL_BUF(0, tb + 10, fb0);

        CP_WAIT_GROUP(1);
        __syncwarp();
        PROCESS_BUF(prd1, tb + SPB, fb1);
        FILL_BUF(1, tb + 15, fb1);
    }

    // tail: steps 360..364 live in buffer0 (refilled at i=35)
    CP_WAIT_GROUP(1);
    __syncwarp();
    PROCESS_BUF(prd0, 360, fb0);
    CP_WAIT_GROUP(0);         // drain before exit
}

// -------------------------------------------------------------------------
// Kernel 2: gamma unit-hydrograph weights per basin (normalized).
// -------------------------------------------------------------------------
__global__ void uh_kernel(const float* __restrict__ conv) {
    const int n = blockIdx.x * blockDim.x + threadIdx.x;
    if (n >= NB) return;
    const float a = conv[n * 2 + 0] * 2.9f;
    const float b = conv[n * 2 + 1] * 6.5f;
    const float aa    = fmaxf(a, 0.0f) + 0.1f;
    const float theta = fmaxf(b, 0.0f) + 0.5f;
    const float lg = lgammaf(aa);
    const float lt = logf(theta);
    const float rth = 1.0f / theta;

    float w[LENF];
    float s = 0.0f;
#pragma unroll
    for (int k = 0; k < LENF; ++k) {
        const float tt = 0.5f + (float)k;
        w[k] = expf(-lg - aa * lt + (aa - 1.0f) * logf(tt) - tt * rth);
        s += w[k];
    }
    const float rs = 1.0f / s;
#pragma unroll
    for (int k = 0; k < LENF; ++k)
        g_uh[k * NB + n] = w[k] * rs;
}

// -------------------------------------------------------------------------
// Kernel 3: 15-tap causal FIR routing, t-tiled x8 (register-resident
// qsim window + uh taps -> ~3x less L2 traffic).
// -------------------------------------------------------------------------
#define TTILE 8
#define NT_TILES ((TT_STEPS + TTILE - 1) / TTILE)   // 46

__global__ void rout_kernel(float* __restrict__ out) {
    const int n = blockIdx.x * blockDim.x + threadIdx.x;
    if (n >= NB) return;
    const int t0 = blockIdx.y * TTILE;

    float uh[LENF];
#pragma unroll
    for (int k = 0; k < LENF; ++k)
        uh[k] = __ldg(&g_uh[k * NB + n]);

    float qs[TTILE + LENF - 1];          // qsim[t0-14 .. t0+7]
#pragma unroll
    for (int i = 0; i < TTILE + LENF - 1; ++i) {
        const int tq = t0 - (LENF - 1) + i;
        qs[i] = (tq >= 0 && tq < TT_STEPS) ? __ldg(&g_qsim[(size_t)tq * NB + n])
                                           : 0.0f;
    }

#pragma unroll
    for (int j = 0; j < TTILE; ++j) {
        const int t = t0 + j;
        if (t < TT_STEPS) {
            float acc = 0.0f;
#pragma unroll
            for (int k = 0; k < LENF; ++k)
                acc += uh[k] * qs[j + (LENF - 1) - k];
            out[(size_t)t * NB + n] = acc;
        }
    }
}

// -------------------------------------------------------------------------
extern "C" void kernel_launch(void* const* d_in, const int* in_sizes, int n_in,
                              void* d_out, int out_size) {
    const float* x    = (const float*)d_in[0];   // (365, 4000, 3)
    const float* praw = (const float*)d_in[1];   // (365, 4000, 16, 4)
    const float* conv = (const float*)d_in[2];   // (4000, 2)
    float* out = (float*)d_out;                  // (365, 4000)

    // 87 KB dynamic smem (> 48 KB default): opt in (idempotent, capture-safe)
    cudaFuncSetAttribute(hbv_scan_kernel,
                         cudaFuncAttributeMaxDynamicSharedMemorySize, SCAN_SMEM);

    hbv_scan_kernel<<<125, 128, SCAN_SMEM>>>(x, praw);
    uh_kernel<<<(NB + 127) / 128, 128>>>(conv);

    dim3 rgrid((NB + 255) / 256, NT_TILES);
    rout_kernel<<<rgrid, 256>>>(out);
}

// round 16
// speedup vs baseline: 1.9393x; 1.0192x over previous
#include <cuda_runtime.h>
#include <cstddef>

#define TT_STEPS 365
#define NB 4000
#define LENF 15

// Scratch (allocation-free: __device__ globals)
__device__ float g_qsim[TT_STEPS * NB];   // mean-over-M runoff per (t, n)
__device__ float g_uh[LENF * NB];         // routing weights per (k, n)

#define SPB 5                             // steps per smem buffer
#define BSTRIDE 68                        // 64 floats + 4 pad -> conflict-free LDS
#define STAGE_FLOATS (8 * BSTRIDE)        // 544 floats per step per warp
#define BUF_FLOATS (SPB * STAGE_FLOATS)   // 2720 floats per buffer
#define WARP_SMEM (2 * BUF_FLOATS)        // two buffers per warp
#define QROW 36                           // qbuf row stride (32 + 4 pad)
#define QBUF_FLOATS (SPB * QROW)          // 180 floats per warp
#define SCAN_SMEM ((4 * WARP_SMEM + 4 * QBUF_FLOATS) * 4)   // 89920 B

__device__ __forceinline__ void cp_async16(unsigned smem_addr, const void* gptr) {
    asm volatile("cp.async.cg.shared.global [%0], [%1], 16;\n"
                 :: "r"(smem_addr), "l"(gptr));
}
__device__ __forceinline__ void cp_commit() {
    asm volatile("cp.async.commit_group;\n");
}
#define CP_WAIT_GROUP(nrem) asm volatile("cp.async.wait_group %0;\n" :: "n"(nrem))

// x^e for x > 0 via direct lg2/ex2 (drops the two ln2/log2e constant FMULs
// from the critical chain vs __expf(e*__logf(x)))
__device__ __forceinline__ float pow_fast(float x, float e) {
    float l, r;
    asm("lg2.approx.f32 %0, %1;" : "=f"(l) : "f"(x));
    l *= e;
    asm("ex2.approx.f32 %0, %1;" : "=f"(r) : "f"(l));
    return r;
}

// -------------------------------------------------------------------------
// HBV step split into PREP (param/forcing-only) and CHAIN (state
// recurrence). The per-step cross-lane mean is REMOVED from the loop:
// each lane stores its raw q to smem; a batched reduce runs per 5 steps.
// -------------------------------------------------------------------------
struct HBVState {
    float SNOWPACK, MELTWATER, SM, SUZ, SLZ;
};

struct Prep {
    float RAIN, SNOW, aM, bR, CWH, FC, rFC, rLPFC,
          BETA, BETAET, PETv, PERC, UZL, K0, K1, K2, Cc;
};

__device__ __forceinline__ Prep prep_step(const float* __restrict__ ps,
                                          float P, float Ta, float PET) {
    float c[14];
#pragma unroll
    for (int i = 0; i < 14; ++i)
        c[i] = ps[i * 4];
    Prep p;
    p.BETA   = 1.0f   + 5.0f    * c[0];
    p.FC     = 50.0f  + 950.0f  * c[1];
    p.K0     = 0.05f  + 0.85f   * c[2];
    p.K1     = 0.01f  + 0.49f   * c[3];
    p.K2     = 0.001f + 0.199f  * c[4];
    const float LP     = 0.2f + 0.8f * c[5];
    p.PERC   = 10.0f  * c[6];
    p.UZL    = 100.0f * c[7];
    const float TTp    = -2.5f + 5.0f * c[8];
    const float CFMAX  = 0.5f + 9.5f * c[9];
    const float CFR    = 0.1f * c[10];
    p.CWH    = 0.2f   * c[11];
    p.BETAET = 0.3f   + 4.7f * c[12];
    p.Cc     = c[13];
    p.rFC    = __fdividef(1.0f, p.FC);
    p.rLPFC  = __fdividef(1.0f, LP * p.FC);
    p.aM     = fmaxf(CFMAX * (Ta - TTp), 0.0f);
    p.bR     = fmaxf(CFR * CFMAX * (TTp - Ta), 0.0f);
    p.RAIN   = (Ta >= TTp) ? P : 0.0f;
    p.SNOW   = (Ta <  TTp) ? P : 0.0f;
    p.PETv   = PET;
    return p;
}

__device__ __forceinline__ void chain_step(HBVState& st, const Prep& p,
                                           float* __restrict__ qsts) {
    // snow / meltwater (X - min(a,X) == max(X-a,0) rewrites, exact)
    const float SP1  = st.SNOWPACK + p.SNOW;
    const float melt = fminf(p.aM, SP1);
    const float MW2  = st.MELTWATER + melt;
    const float SP2  = fmaxf(SP1 - p.aM, 1e-5f);
    const float refreeze = fminf(p.bR, MW2);
    st.SNOWPACK = SP2 + refreeze;
    const float MW3 = fmaxf(MW2 - p.bR, 1e-5f);
    const float cM  = p.CWH * st.SNOWPACK;
    const float tosoil = fmaxf(MW3 - cM, 0.0f);
    st.MELTWATER = fmaxf(fminf(MW3, cM), 1e-5f);

    // soil moisture (pow outputs are >= 0, so only the upper clip is needed)
    const float rt = p.RAIN + tosoil;
    const float sw = fminf(pow_fast(st.SM * p.rFC, p.BETA), 1.0f);
    const float recharge = rt * sw;
    const float SM1 = st.SM + rt - recharge;
    const float excess = fmaxf(SM1 - p.FC, 0.0f);
    const float SM2 = fmaxf(fminf(SM1, p.FC), 1e-5f);

    const float ef = fminf(pow_fast(SM2 * p.rLPFC, p.BETAET), 1.0f);
    const float SM3 = fmaxf(SM2 - p.PETv * ef, 1e-5f);

    const float cap = fminf(st.SLZ,
                            p.Cc * st.SLZ * (1.0f - fminf(SM3 * p.rFC, 1.0f)));
    st.SM = SM3 + cap;
    const float SLZ2 = fmaxf(st.SLZ - cap, 1e-5f);

    // runoff
    const float SUZ1  = st.SUZ + recharge + excess;
    const float PERCa = fminf(SUZ1, p.PERC);
    const float SUZ2  = SUZ1 - PERCa;
    const float Q0 = p.K0 * fmaxf(SUZ2 - p.UZL, 0.0f);
    const float SUZ3 = SUZ2 - Q0;
    const float Q1 = p.K1 * SUZ3;
    st.SUZ = SUZ3 - Q1;
    const float SLZ3 = SLZ2 + PERCa;
    const float Q2 = p.K2 * SLZ3;
    st.SLZ = SLZ3 - Q2;

    // raw per-member runoff -> smem; reduced in a batch every 5 steps
    *qsts = Q0 + Q1 + Q2;
}

// -------------------------------------------------------------------------
// Kernel 1: HBV scan. One thread per (n, m) chain; 16000 threads, 125
// blocks x 128 -> 1 warp per SMSP on every SM (proven wall-optimal).
// Two 5-step smem buffers (one cp.async group each); PREP(s+1) pipelined
// ahead of CHAIN(s); cross-lane ensemble mean batched per 5 steps.
// -------------------------------------------------------------------------
__global__ void __launch_bounds__(128, 1)
hbv_scan_kernel(const float* __restrict__ x,        // (T, N, 3)
                const float* __restrict__ praw) {   // (T, N, 16, 4)
    extern __shared__ __align__(16) float sp[];

    const int lane = threadIdx.x & 31;
    const int wrp  = threadIdx.x >> 5;
    const int tid  = blockIdx.x * 128 + threadIdx.x;   // exactly 16000

    const int n_local = lane >> 2;       // basin within warp (0..7)
    const int n0      = (tid >> 5) * 8;  // warp's first basin
    const int n       = n0 + n_local;
    const int m       = lane & 3;

    float* wbase = sp + wrp * WARP_SMEM;
    float* qb    = sp + 4 * WARP_SMEM + wrp * QBUF_FLOATS;   // [SPB][QROW]

    // producer: lane L copies 16-byte chunks c = j*32 + L (j = 0..3) of the
    // warp's 2048-byte param block (per step)
    unsigned sdst[4];
    const float* gsrc[4];
#pragma unroll
    for (int j = 0; j < 4; ++j) {
        const int c = j * 32 + lane;
        sdst[j] = (unsigned)__cvta_generic_to_shared(
                      wbase + (c >> 4) * BSTRIDE + (c & 15) * 4);
        gsrc[j] = praw + (size_t)n0 * 64 + (size_t)c * 4;
    }
    const unsigned stage_bytes = STAGE_FLOATS * 4;
    const unsigned buf_bytes   = BUF_FLOATS * 4;

    const float* xbase = x + (size_t)n * 3;
    const float* prd0  = wbase + n_local * BSTRIDE + m;            // buffer 0
    const float* prd1  = prd0 + BUF_FLOATS;                        // buffer 1

    HBVState st = {0.001f, 0.001f, 0.001f, 0.001f, 0.001f};

    float fb0[SPB][3], fb1[SPB][3];      // forcings, statically indexed

    // reduce-phase addressing: lane L covers (step L>>3, basin L&7);
    // lanes 0..7 additionally cover step 4.
    const int rs0 = lane >> 3;           // 0..3
    const int rb0 = lane & 7;            // 0..7

#define FILL_BUF(BSEL, TBASE, FB)                                          \
    {                                                                      \
        _Pragma("unroll")                                                  \
        for (int s_ = 0; s_ < SPB; ++s_) {                                 \
            const int tn_ = ((TBASE) + s_ < TT_STEPS) ? (TBASE) + s_       \
                                                      : (TT_STEPS - 1);    \
            const size_t poff_ = (size_t)tn_ * (NB * 64);                  \
            _Pragma("unroll")                                              \
            for (int j_ = 0; j_ < 4; ++j_)                                 \
                cp_async16(sdst[j_] + (BSEL) * buf_bytes                   \
                                    + s_ * stage_bytes,                    \
                           gsrc[j_] + poff_);                              \
            const size_t xoff_ = (size_t)tn_ * (NB * 3);                   \
            _Pragma("unroll")                                              \
            for (int c_ = 0; c_ < 3; ++c_)                                 \
                FB[s_][c_] = __ldg(xbase + xoff_ + c_);                    \
        }                                                                  \
        cp_commit();                                                       \
    }

// PREP(s+1) textually precedes CHAIN(s); q goes to smem (no SHFL tail).
#define PROCESS_BUF(PRD, FB)                                               \
    {                                                                      \
        Prep pc_ = prep_step((PRD), FB[0][0], FB[0][1], FB[0][2]);         \
        _Pragma("unroll")                                                  \
        for (int s_ = 0; s_ < SPB; ++s_) {                                 \
            Prep pn_ = pc_;                                                \
            if (s_ < SPB - 1)                                              \
                pn_ = prep_step((PRD) + (s_ + 1) * STAGE_FLOATS,           \
                                FB[s_ + 1][0], FB[s_ + 1][1],              \
                                FB[s_ + 1][2]);                            \
            chain_step(st, pc_, qb + s_ * QROW + lane);                    \
            pc_ = pn_;                                                     \
        }                                                                  \
    }

// Batched ensemble mean: same pair-then-quad add order as the old shuffle
// tree (bitwise identical). LDS.128 is phase-conflict-free by layout.
#define REDUCE_BUF(TBASE)                                                  \
    {                                                                      \
        __syncwarp();                                                      \
        const float4 v_ = *(const float4*)(qb + rs0 * QROW + rb0 * 4);     \
        g_qsim[(size_t)((TBASE) + rs0) * NB + n0 + rb0] =                  \
            0.25f * ((v_.x + v_.y) + (v_.z + v_.w));                       \
        if (lane < 8) {                                                    \
            const float4 u_ = *(const float4*)(qb + 4 * QROW + lane * 4);  \
            g_qsim[(size_t)((TBASE) + 4) * NB + n0 + lane] =               \
                0.25f * ((u_.x + u_.y) + (u_.z + u_.w));                   \
        }                                                                  \
    }

    // prologue: buffer0 <- t 0..4 (group0), buffer1 <- t 5..9 (group1)
    FILL_BUF(0, 0, fb0);
    FILL_BUF(1, SPB, fb1);

    // 36 iterations x 10 steps + 5-step tail = 365
    for (int i = 0; i < 36; ++i) {
        const int tb = i * 10;

        CP_WAIT_GROUP(1);
        __syncwarp();
        PROCESS_BUF(prd0, fb0);
        REDUCE_BUF(tb);
        FILL_BUF(0, tb + 10, fb0);

        CP_WAIT_GROUP(1);
        __syncwarp();                     // also orders qbuf reuse
        PROCESS_BUF(prd1, fb1);
        REDUCE_BUF(tb + SPB);
        FILL_BUF(1, tb + 15, fb1);
    }

    // tail: steps 360..364 live in buffer0 (refilled at i=35)
    CP_WAIT_GROUP(1);
    __syncwarp();
    PROCESS_BUF(prd0, fb0);
    REDUCE_BUF(360);
    CP_WAIT_GROUP(0);         // drain before exit
}

// -------------------------------------------------------------------------
// Kernel 2: gamma unit-hydrograph weights per basin (normalized).
// -------------------------------------------------------------------------
__global__ void uh_kernel(const float* __restrict__ conv) {
    const int n = blockIdx.x * blockDim.x + threadIdx.x;
    if (n >= NB) return;
    const float a = conv[n * 2 + 0] * 2.9f;
    const float b = conv[n * 2 + 1] * 6.5f;
    const float aa    = fmaxf(a, 0.0f) + 0.1f;
    const float theta = fmaxf(b, 0.0f) + 0.5f;
    const float lg = lgammaf(aa);
    const float lt = logf(theta);
    const float rth = 1.0f / theta;

    float w[LENF];
    float s = 0.0f;
#pragma unroll
    for (int k = 0; k < LENF; ++k) {
        const float tt = 0.5f + (float)k;
        w[k] = expf(-lg - aa * lt + (aa - 1.0f) * logf(tt) - tt * rth);
        s += w[k];
    }
    const float rs = 1.0f / s;
#pragma unroll
    for (int k = 0; k < LENF; ++k)
        g_uh[k * NB + n] = w[k] * rs;
}

// -------------------------------------------------------------------------
// Kernel 3: 15-tap causal FIR routing, t-tiled x8 (register-resident
// qsim window + uh taps -> ~3x less L2 traffic).
// -------------------------------------------------------------------------
#define TTILE 8
#define NT_TILES ((TT_STEPS + TTILE - 1) / TTILE)   // 46

__global__ void rout_kernel(float* __restrict__ out) {
    const int n = blockIdx.x * blockDim.x + threadIdx.x;
    if (n >= NB) return;
    const int t0 = blockIdx.y * TTILE;

    float uh[LENF];
#pragma unroll
    for (int k = 0; k < LENF; ++k)
        uh[k] = __ldg(&g_uh[k * NB + n]);

    float qs[TTILE + LENF - 1];          // qsim[t0-14 .. t0+7]
#pragma unroll
    for (int i = 0; i < TTILE + LENF - 1; ++i) {
        const int tq = t0 - (LENF - 1) + i;
        qs[i] = (tq >= 0 && tq < TT_STEPS) ? __ldg(&g_qsim[(size_t)tq * NB + n])
                                           : 0.0f;
    }

#pragma unroll
    for (int j = 0; j < TTILE; ++j) {
        const int t = t0 + j;
        if (t < TT_STEPS) {
            float acc = 0.0f;
#pragma unroll
            for (int k = 0; k < LENF; ++k)
                acc += uh[k] * qs[j + (LENF - 1) - k];
            out[(size_t)t * NB + n] = acc;
        }
    }
}

// -------------------------------------------------------------------------
extern "C" void kernel_launch(void* const* d_in, const int* in_sizes, int n_in,
                              void* d_out, int out_size) {
    const float* x    = (const float*)d_in[0];   // (365, 4000, 3)
    const float* praw = (const float*)d_in[1];   // (365, 4000, 16, 4)
    const float* conv = (const float*)d_in[2];   // (4000, 2)
    float* out = (float*)d_out;                  // (365, 4000)

    // ~88 KB dynamic smem (> 48 KB default): opt in (idempotent, capture-safe)
    cudaFuncSetAttribute(hbv_scan_kernel,
                         cudaFuncAttributeMaxDynamicSharedMemorySize, SCAN_SMEM);

    hbv_scan_kernel<<<125, 128, SCAN_SMEM>>>(x, praw);
    uh_kernel<<<(NB + 127) / 128, 128>>>(conv);

    dim3 rgrid((NB + 255) / 256, NT_TILES);
    rout_kernel<<<rgrid, 256>>>(out);
}

// round 17
// speedup vs baseline: 1.9779x; 1.0199x over previous
#include <cuda_runtime.h>
#include <cstddef>

#define TT_STEPS 365
#define NB 4000
#define LENF 15

// Scratch (allocation-free: __device__ globals)
__device__ float g_qsim[TT_STEPS * NB];   // mean-over-M runoff per (t, n)
__device__ float g_uh[LENF * NB];         // routing weights per (k, n)

#define SPB 5                             // steps per smem buffer
#define BSTRIDE 68                        // 64 floats + 4 pad -> conflict-free LDS
#define STAGE_FLOATS (8 * BSTRIDE)        // 544 floats per step per warp
#define BUF_FLOATS (SPB * STAGE_FLOATS)   // 2720 floats per buffer
#define WARP_SMEM (2 * BUF_FLOATS)        // two buffers per warp
#define QROW 36                           // qbuf row stride (32 + 4 pad)
#define QBUF_FLOATS (SPB * QROW)          // 180 floats per warp
#define SCAN_SMEM ((4 * WARP_SMEM + 4 * QBUF_FLOATS) * 4)   // 89920 B

__device__ __forceinline__ void cp_async16(unsigned smem_addr, const void* gptr) {
    asm volatile("cp.async.cg.shared.global [%0], [%1], 16;\n"
                 :: "r"(smem_addr), "l"(gptr));
}
__device__ __forceinline__ void cp_commit() {
    asm volatile("cp.async.commit_group;\n");
}
#define CP_WAIT_GROUP(nrem) asm volatile("cp.async.wait_group %0;\n" :: "n"(nrem))

__device__ __forceinline__ float lg2f(float x) {
    float l;
    asm("lg2.approx.f32 %0, %1;" : "=f"(l) : "f"(x));
    return l;
}
__device__ __forceinline__ float ex2f(float x) {
    float r;
    asm("ex2.approx.f32 %0, %1;" : "=f"(r) : "f"(x));
    return r;
}

// -------------------------------------------------------------------------
// HBV step split three ways:
//   PREP  (param/forcing only, no state)        -- pipelined 1 ahead
//   SNOW  (snow-state sub-chain -> rt)          -- pipelined 1 ahead
//   SOIL  (SM/SUZ/SLZ sub-chain, consumes rt)   -- current step
// SNOW(t+1) is independent of SOIL(t) -> two live chains overlap.
// -------------------------------------------------------------------------
struct SnowState { float SNOWPACK, MELTWATER; };
struct SoilState { float SM, SUZ, SLZ; };

struct Prep {
    float RAIN, SNOW, aM, bR, CWH, FC, rFC,
          BETA, c1, BETAET, c2, PETv, PERC, UZL, K0, K1, K2, Cc;
};

__device__ __forceinline__ Prep prep_step(const float* __restrict__ ps,
                                          float P, float Ta, float PET) {
    float c[14];
#pragma unroll
    for (int i = 0; i < 14; ++i)
        c[i] = ps[i * 4];
    Prep p;
    p.BETA   = 1.0f   + 5.0f    * c[0];
    p.FC     = 50.0f  + 950.0f  * c[1];
    p.K0     = 0.05f  + 0.85f   * c[2];
    p.K1     = 0.01f  + 0.49f   * c[3];
    p.K2     = 0.001f + 0.199f  * c[4];
    const float LP     = 0.2f + 0.8f * c[5];
    p.PERC   = 10.0f  * c[6];
    p.UZL    = 100.0f * c[7];
    const float TTp    = -2.5f + 5.0f * c[8];
    const float CFMAX  = 0.5f + 9.5f * c[9];
    const float CFR    = 0.1f * c[10];
    p.CWH    = 0.2f   * c[11];
    p.BETAET = 0.3f   + 4.7f * c[12];
    p.Cc     = c[13];
    p.rFC    = __fdividef(1.0f, p.FC);
    // pow decomposition constants (off-chain):
    //   sw = ex2(BETA  * lg2(SM)  + c1), c1 = -BETA  * lg2(FC)
    //   ef = ex2(BETAET* lg2(SM2) + c2), c2 = -BETAET* lg2(LP*FC)
    p.c1     = -p.BETA   * lg2f(p.FC);
    p.c2     = -p.BETAET * lg2f(LP * p.FC);
    p.aM     = fmaxf(CFMAX * (Ta - TTp), 0.0f);
    p.bR     = fmaxf(CFR * CFMAX * (TTp - Ta), 0.0f);
    p.RAIN   = (Ta >= TTp) ? P : 0.0f;
    p.SNOW   = (Ta <  TTp) ? P : 0.0f;
    p.PETv   = PET;
    return p;
}

// snow sub-chain: touches only SnowState; returns rt = RAIN + tosoil
__device__ __forceinline__ float snow_step(SnowState& sn, const Prep& p) {
    const float SP1  = sn.SNOWPACK + p.SNOW;
    const float melt = fminf(p.aM, SP1);
    const float MW2  = sn.MELTWATER + melt;
    const float SP2  = fmaxf(SP1 - p.aM, 1e-5f);
    const float refreeze = fminf(p.bR, MW2);
    sn.SNOWPACK = SP2 + refreeze;
    const float MW3 = fmaxf(MW2 - p.bR, 1e-5f);
    const float cM  = p.CWH * sn.SNOWPACK;
    const float tosoil = fmaxf(MW3 - cM, 0.0f);
    sn.MELTWATER = fmaxf(fminf(MW3, cM), 1e-5f);
    return p.RAIN + tosoil;
}

// soil sub-chain: consumes rt; touches SM/SUZ/SLZ; writes raw q to smem
__device__ __forceinline__ void soil_step(SoilState& st, const Prep& p,
                                          float rt, float* __restrict__ qsts) {
    const float sw = fminf(ex2f(fmaf(p.BETA, lg2f(st.SM), p.c1)), 1.0f);
    const float recharge = rt * sw;
    const float SM1 = st.SM + rt - recharge;
    const float excess = fmaxf(SM1 - p.FC, 0.0f);
    const float SM2 = fmaxf(fminf(SM1, p.FC), 1e-5f);

    const float ef = fminf(ex2f(fmaf(p.BETAET, lg2f(SM2), p.c2)), 1.0f);
    const float SM3 = fmaxf(SM2 - p.PETv * ef, 1e-5f);

    const float cap = fminf(st.SLZ,
                            p.Cc * st.SLZ * (1.0f - fminf(SM3 * p.rFC, 1.0f)));
    st.SM = SM3 + cap;
    const float SLZ2 = fmaxf(st.SLZ - cap, 1e-5f);

    const float SUZ1  = st.SUZ + recharge + excess;
    const float PERCa = fminf(SUZ1, p.PERC);
    const float SUZ2  = SUZ1 - PERCa;
    const float Q0 = p.K0 * fmaxf(SUZ2 - p.UZL, 0.0f);
    const float SUZ3 = SUZ2 - Q0;
    const float Q1 = p.K1 * SUZ3;
    st.SUZ = SUZ3 - Q1;
    const float SLZ3 = SLZ2 + PERCa;
    const float Q2 = p.K2 * SLZ3;
    st.SLZ = SLZ3 - Q2;

    *qsts = Q0 + Q1 + Q2;
}

// -------------------------------------------------------------------------
// Kernel 1: HBV scan. One thread per (n, m) chain; 16000 threads, 125
// blocks x 128 -> 1 warp per SMSP (proven wall-optimal). Two 5-step smem
// buffers; within a buffer: PREP(s+1) and SNOW(s+1) run ahead of SOIL(s).
// -------------------------------------------------------------------------
__global__ void __launch_bounds__(128, 1)
hbv_scan_kernel(const float* __restrict__ x,        // (T, N, 3)
                const float* __restrict__ praw) {   // (T, N, 16, 4)
    extern __shared__ __align__(16) float sp[];

    const int lane = threadIdx.x & 31;
    const int wrp  = threadIdx.x >> 5;
    const int tid  = blockIdx.x * 128 + threadIdx.x;   // exactly 16000

    const int n_local = lane >> 2;       // basin within warp (0..7)
    const int n0      = (tid >> 5) * 8;  // warp's first basin
    const int n       = n0 + n_local;
    const int m       = lane & 3;

    float* wbase = sp + wrp * WARP_SMEM;
    float* qb    = sp + 4 * WARP_SMEM + wrp * QBUF_FLOATS;   // [SPB][QROW]

    unsigned sdst[4];
    const float* gsrc[4];
#pragma unroll
    for (int j = 0; j < 4; ++j) {
        const int c = j * 32 + lane;
        sdst[j] = (unsigned)__cvta_generic_to_shared(
                      wbase + (c >> 4) * BSTRIDE + (c & 15) * 4);
        gsrc[j] = praw + (size_t)n0 * 64 + (size_t)c * 4;
    }
    const unsigned stage_bytes = STAGE_FLOATS * 4;
    const unsigned buf_bytes   = BUF_FLOATS * 4;

    const float* xbase = x + (size_t)n * 3;
    const float* prd0  = wbase + n_local * BSTRIDE + m;            // buffer 0
    const float* prd1  = prd0 + BUF_FLOATS;                        // buffer 1

    SnowState sn = {0.001f, 0.001f};
    SoilState st = {0.001f, 0.001f, 0.001f};

    float fb0[SPB][3], fb1[SPB][3];      // forcings, statically indexed

    const int rs0 = lane >> 3;           // reduce: step 0..3
    const int rb0 = lane & 7;            // reduce: basin 0..7

#define FILL_BUF(BSEL, TBASE, FB)                                          \
    {                                                                      \
        _Pragma("unroll")                                                  \
        for (int s_ = 0; s_ < SPB; ++s_) {                                 \
            const int tn_ = ((TBASE) + s_ < TT_STEPS) ? (TBASE) + s_       \
                                                      : (TT_STEPS - 1);    \
            const size_t poff_ = (size_t)tn_ * (NB * 64);                  \
            _Pragma("unroll")                                              \
            for (int j_ = 0; j_ < 4; ++j_)                                 \
                cp_async16(sdst[j_] + (BSEL) * buf_bytes                   \
                                    + s_ * stage_bytes,                    \
                           gsrc[j_] + poff_);                              \
            const size_t xoff_ = (size_t)tn_ * (NB * 3);                   \
            _Pragma("unroll")                                              \
            for (int c_ = 0; c_ < 3; ++c_)                                 \
                FB[s_][c_] = __ldg(xbase + xoff_ + c_);                    \
        }                                                                  \
        cp_commit();                                                       \
    }

// Pipeline: PREP(s+1) and SNOW(s+1) (independent of soil state) textually
// precede SOIL(s); the two live chains overlap in the in-order schedule.
#define PROCESS_BUF(PRD, FB)                                               \
    {                                                                      \
        Prep  pc_ = prep_step((PRD), FB[0][0], FB[0][1], FB[0][2]);        \
        float rt_c_ = snow_step(sn, pc_);                                  \
        _Pragma("unroll")                                                  \
        for (int s_ = 0; s_ < SPB; ++s_) {                                 \
            Prep  pn_   = pc_;                                             \
            float rt_n_ = rt_c_;                                           \
            if (s_ < SPB - 1) {                                            \
                pn_ = prep_step((PRD) + (s_ + 1) * STAGE_FLOATS,           \
                                FB[s_ + 1][0], FB[s_ + 1][1],              \
                                FB[s_ + 1][2]);                            \
                rt_n_ = snow_step(sn, pn_);                                \
            }                                                              \
            soil_step(st, pc_, rt_c_, qb + s_ * QROW + lane);              \
            pc_ = pn_;                                                     \
            rt_c_ = rt_n_;                                                 \
        }                                                                  \
    }

#define REDUCE_BUF(TBASE)                                                  \
    {                                                                      \
        __syncwarp();                                                      \
        const float4 v_ = *(const float4*)(qb + rs0 * QROW + rb0 * 4);     \
        g_qsim[(size_t)((TBASE) + rs0) * NB + n0 + rb0] =                  \
            0.25f * ((v_.x + v_.y) + (v_.z + v_.w));                       \
        if (lane < 8) {                                                    \
            const float4 u_ = *(const float4*)(qb + 4 * QROW + lane * 4);  \
            g_qsim[(size_t)((TBASE) + 4) * NB + n0 + lane] =               \
                0.25f * ((u_.x + u_.y) + (u_.z + u_.w));                   \
        }                                                                  \
    }

    // prologue: buffer0 <- t 0..4 (group0), buffer1 <- t 5..9 (group1)
    FILL_BUF(0, 0, fb0);
    FILL_BUF(1, SPB, fb1);

    // 36 iterations x 10 steps + 5-step tail = 365
    for (int i = 0; i < 36; ++i) {
        const int tb = i * 10;

        CP_WAIT_GROUP(1);
        __syncwarp();
        PROCESS_BUF(prd0, fb0);
        REDUCE_BUF(tb);
        FILL_BUF(0, tb + 10, fb0);

        CP_WAIT_GROUP(1);
        __syncwarp();                     // also orders qbuf reuse
        PROCESS_BUF(prd1, fb1);
        REDUCE_BUF(tb + SPB);
        FILL_BUF(1, tb + 15, fb1);
    }

    // tail: steps 360..364 live in buffer0 (refilled at i=35)
    CP_WAIT_GROUP(1);
    __syncwarp();
    PROCESS_BUF(prd0, fb0);
    REDUCE_BUF(360);
    CP_WAIT_GROUP(0);         // drain before exit
}

// -------------------------------------------------------------------------
// Kernel 2: gamma unit-hydrograph weights per basin (normalized).
// -------------------------------------------------------------------------
__global__ void uh_kernel(const float* __restrict__ conv) {
    const int n = blockIdx.x * blockDim.x + threadIdx.x;
    if (n >= NB) return;
    const float a = conv[n * 2 + 0] * 2.9f;
    const float b = conv[n * 2 + 1] * 6.5f;
    const float aa    = fmaxf(a, 0.0f) + 0.1f;
    const float theta = fmaxf(b, 0.0f) + 0.5f;
    const float lg = lgammaf(aa);
    const float lt = logf(theta);
    const float rth = 1.0f / theta;

    float w[LENF];
    float s = 0.0f;
#pragma unroll
    for (int k = 0; k < LENF; ++k) {
        const float tt = 0.5f + (float)k;
        w[k] = expf(-lg - aa * lt + (aa - 1.0f) * logf(tt) - tt * rth);
        s += w[k];
    }
    const float rs = 1.0f / s;
#pragma unroll
    for (int k = 0; k < LENF; ++k)
        g_uh[k * NB + n] = w[k] * rs;
}

// -------------------------------------------------------------------------
// Kernel 3: 15-tap causal FIR routing, t-tiled x8.
// -------------------------------------------------------------------------
#define TTILE 8
#define NT_TILES ((TT_STEPS + TTILE - 1) / TTILE)   // 46

__global__ void rout_kernel(float* __restrict__ out) {
    const int n = blockIdx.x * blockDim.x + threadIdx.x;
    if (n >= NB) return;
    const int t0 = blockIdx.y * TTILE;

    float uh[LENF];
#pragma unroll
    for (int k = 0; k < LENF; ++k)
        uh[k] = __ldg(&g_uh[k * NB + n]);

    float qs[TTILE + LENF - 1];          // qsim[t0-14 .. t0+7]
#pragma unroll
    for (int i = 0; i < TTILE + LENF - 1; ++i) {
        const int tq = t0 - (LENF - 1) + i;
        qs[i] = (tq >= 0 && tq < TT_STEPS) ? __ldg(&g_qsim[(size_t)tq * NB + n])
                                           : 0.0f;
    }

#pragma unroll
    for (int j = 0; j < TTILE; ++j) {
        const int t = t0 + j;
        if (t < TT_STEPS) {
            float acc = 0.0f;
#pragma unroll
            for (int k = 0; k < LENF; ++k)
                acc += uh[k] * qs[j + (LENF - 1) - k];
            out[(size_t)t * NB + n] = acc;
        }
    }
}

// -------------------------------------------------------------------------
extern "C" void kernel_launch(void* const* d_in, const int* in_sizes, int n_in,
                              void* d_out, int out_size) {
    const float* x    = (const float*)d_in[0];   // (365, 4000, 3)
    const float* praw = (const float*)d_in[1];   // (365, 4000, 16, 4)
    const float* conv = (const float*)d_in[2];   // (4000, 2)
    float* out = (float*)d_out;                  // (365, 4000)

    // ~88 KB dynamic smem (> 48 KB default): opt in (idempotent, capture-safe)
    cudaFuncSetAttribute(hbv_scan_kernel,
                         cudaFuncAttributeMaxDynamicSharedMemorySize, SCAN_SMEM);

    hbv_scan_kernel<<<125, 128, SCAN_SMEM>>>(x, praw);
    uh_kernel<<<(NB + 127) / 128, 128>>>(conv);

    dim3 rgrid((NB + 255) / 256, NT_TILES);
    rout_kernel<<<rgrid, 256>>>(out);
}